// round 3
// baseline (speedup 1.0000x reference)
#include <cuda_runtime.h>
#include <cstdint>

#define B 16
#define I 256
#define T 8192
#define NSTEP 8189   // T-3 sampled steps
#define TOUT  8190   // T-2 output length

// Scratch (static __device__ arrays; no allocation anywhere)
__device__ unsigned char g_nsp[B * T];       // [b][t]: bits0-1 = normal sample, bit2 = special sample - 1
__device__ unsigned char g_delta[B * T];     // [b][jo]: gather delta in {0,1,2}

// ---------------- Threefry-2x32 (JAX-exact) ----------------
__device__ __forceinline__ void tf2x32(uint32_t k1, uint32_t k2,
                                       uint32_t c0, uint32_t c1,
                                       uint32_t& o0, uint32_t& o1) {
    uint32_t ks2 = k1 ^ k2 ^ 0x1BD11BDAu;
    uint32_t x0 = c0 + k1;
    uint32_t x1 = c1 + k2;
#define TFR(r) { x0 += x1; x1 = __funnelshift_l(x1, x1, (r)); x1 ^= x0; }
    TFR(13) TFR(15) TFR(26) TFR(6)
    x0 += k2;  x1 += ks2 + 1u;
    TFR(17) TFR(29) TFR(16) TFR(24)
    x0 += ks2; x1 += k1 + 2u;
    TFR(13) TFR(15) TFR(26) TFR(6)
    x0 += k1;  x1 += k2 + 3u;
    TFR(17) TFR(29) TFR(16) TFR(24)
    x0 += k2;  x1 += ks2 + 4u;
    TFR(13) TFR(15) TFR(26) TFR(6)
    x0 += ks2; x1 += k1 + 5u;
#undef TFR
    o0 = x0; o1 = x1;
}

// gumbel from 32 random bits, replicating jax._src.random._uniform + gumbel
__device__ __forceinline__ float gumbel_bits(uint32_t bits) {
    const float TINY = 1.17549435e-38f;   // finfo(float32).tiny
    float f = __uint_as_float((bits >> 9) | 0x3F800000u) - 1.0f;  // [0,1)
    float u = fmaxf(TINY, f + TINY);
    return -logf(-logf(u));
}

// ---------------- Kernel 1: per-(t,b) normal & special samples ----------------
// Per-step key computed inline (fold-like partitionable split): 16x redundant
// threefry per t, but saves a kernel launch + global round-trip.
__global__ void kgen(const int* __restrict__ seedp) {
    int t = blockIdx.x * blockDim.x + threadIdx.x;
    int b = blockIdx.y;
    if (t >= NSTEP) return;

    uint32_t seed_lo = (uint32_t)(*seedp);  // threefry_seed: k1 = seed>>32 = 0
    uint32_t kx, ky;
    tf2x32(0u, seed_lo, 0u, (uint32_t)t, kx, ky);   // split -> per-step key

    float g0, g1, g2;
    {
        uint32_t o0, o1;
        tf2x32(kx, ky, 0u, (uint32_t)(b * 3 + 0), o0, o1);
        g0 = gumbel_bits(o0 ^ o1);
        tf2x32(kx, ky, 0u, (uint32_t)(b * 3 + 1), o0, o1);
        g1 = gumbel_bits(o0 ^ o1);
        tf2x32(kx, ky, 0u, (uint32_t)(b * 3 + 2), o0, o1);
        g2 = gumbel_bits(o0 ^ o1);
    }

    const double pd = 0.1, sd = 1.0 - 2.0 * 0.1;
    float lp  = logf(0.1f);
    float ls  = logf(0.8f);
    float l1s = logf((float)(sd / (pd + sd)));  // special row k=1
    float l2s = logf((float)(pd / (pd + sd)));  // special row k=2  (k=0 is -inf)

    // normal row argmax (first max wins)
    float v0 = g0 + lp, v1 = g1 + ls, v2 = g2 + lp;
    int n = 0; float best = v0;
    if (v1 > best) { best = v1; n = 1; }
    if (v2 > best) { n = 2; }

    // special row argmax over {1,2} (index 0 has -inf logit)
    int sp = (g2 + l2s > g1 + l1s) ? 2 : 1;

    g_nsp[b * T + t] = (unsigned char)(n | ((sp - 1) << 2));
}

// ---------------- Kernel 2: parallel FSM scan per batch ----------------
// state v = 3*p2 + p1 in [0,9); special state is v==5 (p2=1,p1=2).
// step: choice = (v==5) ? sp : n ; v' = 3*(v%3) + choice.
// After one step any state collapses to a function of class(v) = (v==5)?3:(v%3).
// 512 threads x 16 steps per chunk (halves the serial chain vs 256x32).
__global__ __launch_bounds__(512) void kscan() {
    int b = blockIdx.x;
    int j = threadIdx.x;               // 0..511, chunk of 16 steps
    __shared__ uint32_t maps[512];

    uint4 wv = *reinterpret_cast<const uint4*>(g_nsp + b * T + j * 16);
    uint32_t w[4] = {wv.x, wv.y, wv.z, wv.w};

    int nvalid = NSTEP - j * 16;
    if (nvalid > 16) nvalid = 16;      // every thread has >= 1 valid step

    // chunk function: class (0..3) -> resulting state
    uint32_t f0, f1, f2, f3;
    {
        uint32_t byt = w[0] & 0xFFu;
        uint32_t n = byt & 3u, sp = 1u + ((byt >> 2) & 1u);
        f0 = n; f1 = 3u + n; f2 = 6u + n; f3 = 6u + sp;
    }
    for (int s = 1; s < nvalid; s++) {
        uint32_t byt = (w[s >> 2] >> ((s & 3) * 8)) & 0xFFu;
        uint32_t n = byt & 3u, sp = 1u + ((byt >> 2) & 1u);
        f0 = (f0 % 3u) * 3u + ((f0 == 5u) ? sp : n);
        f1 = (f1 % 3u) * 3u + ((f1 == 5u) ? sp : n);
        f2 = (f2 % 3u) * 3u + ((f2 == 5u) ? sp : n);
        f3 = (f3 % 3u) * 3u + ((f3 == 5u) ? sp : n);
    }
    maps[j] = f0 | (f1 << 8) | (f2 << 16) | (f3 << 24);
    __syncthreads();

    // Hillis-Steele inclusive scan of chunk-function composition
    for (int off = 1; off < 512; off <<= 1) {
        uint32_t prev = (j >= off) ? maps[j - off] : 0u;
        __syncthreads();
        if (j >= off) {
            uint32_t cur = maps[j];
            uint32_t nm = 0u;
#pragma unroll
            for (int c = 0; c < 4; c++) {
                uint32_t pv = (prev >> (8 * c)) & 0xFFu;
                uint32_t cl = (pv == 5u) ? 3u : (pv % 3u);
                nm |= (((cur >> (8 * cl)) & 0xFFu) << (8 * c));
            }
            maps[j] = nm;
        }
        __syncthreads();
    }

    // entry state: apply prefix (chunks 0..j-1) to init state 4 (class 1)
    uint32_t v = (j == 0) ? 4u : ((maps[j - 1] >> 8) & 0xFFu);

    unsigned char* dp = g_delta + b * T;
    if (j == 0) dp[0] = 1;             // jo=0 fixed index 1
#pragma unroll
    for (int s = 0; s < 16; s++) {
        int t = j * 16 + s;
        if (t < NSTEP) {
            uint32_t byt = (w[s >> 2] >> ((s & 3) * 8)) & 0xFFu;
            uint32_t n = byt & 3u, sp = 1u + ((byt >> 2) & 1u);
            uint32_t ch = (v == 5u) ? sp : n;
            dp[t + 1] = (unsigned char)ch;
            v = (v % 3u) * 3u + ch;
        }
    }
}

// ---------------- Kernel 3: register-only gather ----------------
// 8 outputs per thread at 8-aligned jo. x window jo..jo+9 via
// float4+float4+float2 (aligned), deltas via one uint2, output as 4 float2.
// No smem, no barriers -> full occupancy, pure streaming.
__global__ __launch_bounds__(256) void kgather(const float* __restrict__ x,
                                               float* __restrict__ y) {
    int chunk = blockIdx.x * 256 + threadIdx.x;   // 1024 chunks per row
    int row = chunk >> 10;                        // b*I + i
    int jo  = (chunk & 1023) << 3;                // 0..8184
    int b   = row >> 8;

    const float* xr = x + (size_t)row * T;
    float4 a = __ldg(reinterpret_cast<const float4*>(xr + jo));
    float4 c = __ldg(reinterpret_cast<const float4*>(xr + jo + 4));
    float2 e = make_float2(0.f, 0.f);
    bool tail = (jo + 8 >= TOUT);                 // only jo == 8184
    if (!tail) e = __ldg(reinterpret_cast<const float2*>(xr + jo + 8));

    uint2 dd = *reinterpret_cast<const uint2*>(g_delta + (size_t)b * T + jo);

    float rr[10] = {a.x, a.y, a.z, a.w, c.x, c.y, c.z, c.w, e.x, e.y};
    float o[8];
#pragma unroll
    for (int q = 0; q < 8; q++) {
        uint32_t d = ((q < 4 ? dd.x >> (8 * q) : dd.y >> (8 * (q - 4))) & 3u);
        o[q] = (d == 0) ? rr[q] : ((d == 1) ? rr[q + 1] : rr[q + 2]);
    }

    float2* yr = reinterpret_cast<float2*>(y + (size_t)row * TOUT + jo);
    yr[0] = make_float2(o[0], o[1]);
    yr[1] = make_float2(o[2], o[3]);
    yr[2] = make_float2(o[4], o[5]);
    if (!tail) yr[3] = make_float2(o[6], o[7]);   // tail row has only 6 valid outputs
}

extern "C" void kernel_launch(void* const* d_in, const int* in_sizes, int n_in,
                              void* d_out, int out_size) {
    const float* x   = (const float*)d_in[0];
    const int* seedp = (const int*)d_in[1];
    float* y = (float*)d_out;

    dim3 gg((NSTEP + 255) / 256, B);
    kgen<<<gg, 256>>>(seedp);
    kscan<<<B, 512>>>();
    kgather<<<(B * I * 1024) / 256, 256>>>(x, y);
}

// round 4
// speedup vs baseline: 1.2524x; 1.2524x over previous
#include <cuda_runtime.h>
#include <cstdint>

#define B 16
#define I 256
#define T 8192
#define NSTEP 8189   // T-3 sampled steps
#define TOUT  8190   // T-2 output length

// Scratch (static __device__ arrays; no allocation anywhere)
__device__ unsigned char g_nsp[B * T];       // [b][t]: bits0-1 = normal sample, bit2 = special sample - 1
__device__ unsigned char g_delta[B * T];     // [b][jo]: gather delta in {0,1,2}

// ---------------- Threefry-2x32 (JAX-exact) ----------------
__device__ __forceinline__ void tf2x32(uint32_t k1, uint32_t k2,
                                       uint32_t c0, uint32_t c1,
                                       uint32_t& o0, uint32_t& o1) {
    uint32_t ks2 = k1 ^ k2 ^ 0x1BD11BDAu;
    uint32_t x0 = c0 + k1;
    uint32_t x1 = c1 + k2;
#define TFR(r) { x0 += x1; x1 = __funnelshift_l(x1, x1, (r)); x1 ^= x0; }
    TFR(13) TFR(15) TFR(26) TFR(6)
    x0 += k2;  x1 += ks2 + 1u;
    TFR(17) TFR(29) TFR(16) TFR(24)
    x0 += ks2; x1 += k1 + 2u;
    TFR(13) TFR(15) TFR(26) TFR(6)
    x0 += k1;  x1 += k2 + 3u;
    TFR(17) TFR(29) TFR(16) TFR(24)
    x0 += k2;  x1 += ks2 + 4u;
    TFR(13) TFR(15) TFR(26) TFR(6)
    x0 += ks2; x1 += k1 + 5u;
#undef TFR
    o0 = x0; o1 = x1;
}

// gumbel from 32 random bits, replicating jax._src.random._uniform + gumbel
__device__ __forceinline__ float gumbel_bits(uint32_t bits) {
    const float TINY = 1.17549435e-38f;   // finfo(float32).tiny
    float f = __uint_as_float((bits >> 9) | 0x3F800000u) - 1.0f;  // [0,1)
    float u = fmaxf(TINY, f + TINY);
    return -logf(-logf(u));
}

// ---------------- Kernel 1: per-(t,b) normal & special samples ----------------
__global__ void kgen(const int* __restrict__ seedp) {
    int t = blockIdx.x * blockDim.x + threadIdx.x;
    int b = blockIdx.y;
    if (t >= NSTEP) return;

    uint32_t seed_lo = (uint32_t)(*seedp);  // threefry_seed: k1 = seed>>32 = 0
    uint32_t kx, ky;
    tf2x32(0u, seed_lo, 0u, (uint32_t)t, kx, ky);   // split -> per-step key

    float g0, g1, g2;
    {
        uint32_t o0, o1;
        tf2x32(kx, ky, 0u, (uint32_t)(b * 3 + 0), o0, o1);
        g0 = gumbel_bits(o0 ^ o1);
        tf2x32(kx, ky, 0u, (uint32_t)(b * 3 + 1), o0, o1);
        g1 = gumbel_bits(o0 ^ o1);
        tf2x32(kx, ky, 0u, (uint32_t)(b * 3 + 2), o0, o1);
        g2 = gumbel_bits(o0 ^ o1);
    }

    const double pd = 0.1, sd = 1.0 - 2.0 * 0.1;
    float lp  = logf(0.1f);
    float ls  = logf(0.8f);
    float l1s = logf((float)(sd / (pd + sd)));  // special row k=1
    float l2s = logf((float)(pd / (pd + sd)));  // special row k=2  (k=0 is -inf)

    // normal row argmax (first max wins)
    float v0 = g0 + lp, v1 = g1 + ls, v2 = g2 + lp;
    int n = 0; float best = v0;
    if (v1 > best) { best = v1; n = 1; }
    if (v2 > best) { n = 2; }

    // special row argmax over {1,2} (index 0 has -inf logit)
    int sp = (g2 + l2s > g1 + l1s) ? 2 : 1;

    g_nsp[b * T + t] = (unsigned char)(n | ((sp - 1) << 2));
}

// ---------------- Kernel 2: parallel FSM scan per batch ----------------
__global__ __launch_bounds__(512) void kscan() {
    int b = blockIdx.x;
    int j = threadIdx.x;               // 0..511, chunk of 16 steps
    __shared__ uint32_t maps[512];

    uint4 wv = *reinterpret_cast<const uint4*>(g_nsp + b * T + j * 16);
    uint32_t w[4] = {wv.x, wv.y, wv.z, wv.w};

    int nvalid = NSTEP - j * 16;
    if (nvalid > 16) nvalid = 16;      // every thread has >= 1 valid step

    // chunk function: class (0..3) -> resulting state
    uint32_t f0, f1, f2, f3;
    {
        uint32_t byt = w[0] & 0xFFu;
        uint32_t n = byt & 3u, sp = 1u + ((byt >> 2) & 1u);
        f0 = n; f1 = 3u + n; f2 = 6u + n; f3 = 6u + sp;
    }
    for (int s = 1; s < nvalid; s++) {
        uint32_t byt = (w[s >> 2] >> ((s & 3) * 8)) & 0xFFu;
        uint32_t n = byt & 3u, sp = 1u + ((byt >> 2) & 1u);
        f0 = (f0 % 3u) * 3u + ((f0 == 5u) ? sp : n);
        f1 = (f1 % 3u) * 3u + ((f1 == 5u) ? sp : n);
        f2 = (f2 % 3u) * 3u + ((f2 == 5u) ? sp : n);
        f3 = (f3 % 3u) * 3u + ((f3 == 5u) ? sp : n);
    }
    maps[j] = f0 | (f1 << 8) | (f2 << 16) | (f3 << 24);
    __syncthreads();

    // Hillis-Steele inclusive scan of chunk-function composition
    for (int off = 1; off < 512; off <<= 1) {
        uint32_t prev = (j >= off) ? maps[j - off] : 0u;
        __syncthreads();
        if (j >= off) {
            uint32_t cur = maps[j];
            uint32_t nm = 0u;
#pragma unroll
            for (int c = 0; c < 4; c++) {
                uint32_t pv = (prev >> (8 * c)) & 0xFFu;
                uint32_t cl = (pv == 5u) ? 3u : (pv % 3u);
                nm |= (((cur >> (8 * cl)) & 0xFFu) << (8 * c));
            }
            maps[j] = nm;
        }
        __syncthreads();
    }

    // entry state: apply prefix (chunks 0..j-1) to init state 4 (class 1)
    uint32_t v = (j == 0) ? 4u : ((maps[j - 1] >> 8) & 0xFFu);

    unsigned char* dp = g_delta + b * T;
    if (j == 0) dp[0] = 1;             // jo=0 fixed index 1
#pragma unroll
    for (int s = 0; s < 16; s++) {
        int t = j * 16 + s;
        if (t < NSTEP) {
            uint32_t byt = (w[s >> 2] >> ((s & 3) * 8)) & 0xFFu;
            uint32_t n = byt & 3u, sp = 1u + ((byt >> 2) & 1u);
            uint32_t ch = (v == 5u) ? sp : n;
            dp[t + 1] = (unsigned char)ch;
            v = (v % 3u) * 3u + ch;
        }
    }
}

// ---------------- Kernel 3: gather via half-row SMEM tiles ----------------
// One block per (row, half). Stage 4096(+16) floats of x (16.4KB) + 4KB delta
// into smem with coalesced float4/uint4 loads -> 20.5KB/block -> 8 blocks/SM
// (full occupancy), shifted gather in SMEM, coalesced float2 stores.
__global__ __launch_bounds__(256) void kgather(const float* __restrict__ x,
                                               float* __restrict__ y) {
    __shared__ float         sx[4112];     // 4096 + 16 halo
    __shared__ unsigned char sd[4096];

    int tid  = threadIdx.x;
    int h    = blockIdx.x & 1;             // half index
    int row  = blockIdx.x >> 1;            // b*I + i
    int b    = row >> 8;
    int base = h << 12;                    // 0 or 4096

    // stage x: 1024 float4 (+4 halo float4 for h=0 only; h=1 ends at row end)
    const float4* xr4 = reinterpret_cast<const float4*>(x + (size_t)row * T + base);
    float4* sx4 = reinterpret_cast<float4*>(sx);
#pragma unroll
    for (int k = 0; k < 4; k++)
        sx4[tid + k * 256] = __ldg(xr4 + tid + k * 256);
    if (h == 0 && tid < 4)
        sx4[1024 + tid] = __ldg(xr4 + 1024 + tid);

    // stage delta: 256 uint4
    const uint4* dr4 = reinterpret_cast<const uint4*>(g_delta + (size_t)b * T + base);
    reinterpret_cast<uint4*>(sd)[tid] = __ldg(dr4 + tid);

    __syncthreads();

    float2* yr2 = reinterpret_cast<float2*>(y + (size_t)row * TOUT + base);
    int nf2 = (h == 0) ? 2048 : 2047;      // h=1 half has 4094 outputs
#pragma unroll
    for (int k = 0; k < 8; k++) {
        int jo2 = tid + k * 256;
        if (jo2 < nf2) {
            int jo = jo2 * 2;
            float v0 = sx[jo + sd[jo]];
            float v1 = sx[jo + 1 + sd[jo + 1]];
            yr2[jo2] = make_float2(v0, v1);
        }
    }
}

extern "C" void kernel_launch(void* const* d_in, const int* in_sizes, int n_in,
                              void* d_out, int out_size) {
    const float* x   = (const float*)d_in[0];
    const int* seedp = (const int*)d_in[1];
    float* y = (float*)d_out;

    dim3 gg((NSTEP + 255) / 256, B);
    kgen<<<gg, 256>>>(seedp);
    kscan<<<B, 512>>>();
    kgather<<<B * I * 2, 256>>>(x, y);
}